// round 1
// baseline (speedup 1.0000x reference)
#include <cuda_runtime.h>
#include <math.h>

#define N_SRC   16384
#define N_DST   8192
#define KNB     16
#define LL      32      // K*T neighbors
#define NODE_IN 128
#define EDGE_IN 64
#define TIME_D  128
#define D_MODEL 320
#define NH      8
#define DK      64
#define HD      512     // NH*DK
#define HID     128
#define DCAT    448

// ---------------- scratch (device globals; no allocations) ----------------
// g_proj rows (16384 x 1536): [0:512)=node_k, [512:1024)=node_v, [1024:1536)=qh (rows<8192 valid)
__device__ float g_proj[(long)N_SRC * 1536];
__device__ float g_packW[128 * 1536];     // [d][r] packed node-cols of w_ks|w_vs|w_qs
__device__ float g_biasq[512];            // sum_d cos(phase_d) * w_qs[:,192+d]
__device__ float g_cosph[128];
__device__ float g_fcwT[512 * 320];       // fc_w transposed
__device__ float g_nodewT[448 * 128];     // node_w transposed
__device__ float g_wvT[8 * 192 * 64];     // per-head V edge|te weights, [h][c][d]
__device__ float g_wfold[(long)N_DST * 1536]; // per n: [h*192 + (0:64 edge, 64:192 te)]
__device__ float g_et[(long)N_DST * 1536];    // per n: [h*192 + (ebar 0:64, tbar 64:192)]
__device__ float g_ctx[(long)N_DST * 512];
__device__ float g_x[(long)N_DST * 320];
__device__ float g_hcat[(long)N_DST * 448];

// ---------------- prep / pack kernel ----------------
__global__ void prep_kernel(const float* __restrict__ wks, const float* __restrict__ wvs,
                            const float* __restrict__ wqs, const float* __restrict__ fcw,
                            const float* __restrict__ nw,  const float* __restrict__ ph)
{
    const int P0 = 196608;            // packW 128*1536
    const int P1 = P0 + 163840;      // fcwT 512*320
    const int P2 = P1 + 57344;       // nodewT 448*128
    const int P3 = P2 + 98304;       // wvT 8*192*64
    const int P4 = P3 + 512;         // biasq
    const int P5 = P4 + 128;         // cosph
    int t = blockIdx.x * blockDim.x + threadIdx.x;
    if (t < P0) {
        int d = t / 1536, r = t % 1536;
        float v;
        if (r < 512)       v = wks[r * 320 + d];
        else if (r < 1024) v = wvs[(r - 512) * 320 + d];
        else               v = wqs[(r - 1024) * 320 + d];
        g_packW[t] = v;
    } else if (t < P1) {
        int i = t - P0; int j = i / 320, c = i % 320;
        g_fcwT[i] = fcw[c * 512 + j];
    } else if (t < P2) {
        int i = t - P1; int c = i / 128, o = i % 128;
        g_nodewT[i] = nw[o * 448 + c];
    } else if (t < P3) {
        int i = t - P2; int h = i / 12288; int rem = i % 12288;
        int c = rem / 64, d = rem % 64;
        g_wvT[i] = wvs[(h * 64 + d) * 320 + 128 + c];
    } else if (t < P4) {
        int j = t - P3;
        float acc = 0.f;
        for (int d = 0; d < 128; d++) acc += cosf(ph[d]) * wqs[j * 320 + 192 + d];
        g_biasq[j] = acc;
    } else if (t < P5) {
        int d = t - P4;
        g_cosph[d] = cosf(ph[d]);
    }
}

// ---------------- generic register-tiled SGEMM: C(=|+=) A @ B ----------------
// A: M x Kd row-major (lda), B: Kd x N row-major (ldb), C: M x N (ldc).
// All dims must be tile multiples (true for every call below).
// EPI: 0 store, 1 accumulate, 3 relu(v+bias), 4 qh-bias (col>=1024), 5 fc epilogue (+bias + residual q)
template<int BM, int BN, int BK, int TM, int TN, int EPI>
__global__ void gemm_k(const float* __restrict__ A, const float* __restrict__ B,
                       float* __restrict__ C,
                       int M, int N, int Kd, int lda, int ldb, int ldc,
                       long bsA, long bsB, long bsC,
                       const float* __restrict__ bias,
                       const float* __restrict__ aux1,
                       const float* __restrict__ aux2)
{
    constexpr int THREADS = (BM / TM) * (BN / TN);
    __shared__ __align__(16) float sA[BK][BM + 4];
    __shared__ __align__(16) float sB[BK][BN + 4];
    const int bz = blockIdx.z;
    A += (long)bz * bsA; B += (long)bz * bsB; C += (long)bz * bsC;
    const int tm0 = blockIdx.y * BM;
    const int tn0 = blockIdx.x * BN;
    const int tid = threadIdx.x;
    const int tcol = tid % (BN / TN);
    const int trow = tid / (BN / TN);

    float acc[TM][TN];
#pragma unroll
    for (int i = 0; i < TM; i++)
#pragma unroll
        for (int j = 0; j < TN; j++) acc[i][j] = 0.f;

    for (int k0 = 0; k0 < Kd; k0 += BK) {
        for (int i = tid; i < BM * BK; i += THREADS) {
            int m = i / BK, kk = i % BK;
            sA[kk][m] = A[(long)(tm0 + m) * lda + k0 + kk];
        }
        for (int i = tid; i < BK * BN; i += THREADS) {
            int kk = i / BN, nn = i % BN;
            sB[kk][nn] = B[(long)(k0 + kk) * ldb + tn0 + nn];
        }
        __syncthreads();
#pragma unroll
        for (int kk = 0; kk < BK; kk++) {
            float av[TM], bv[TN];
#pragma unroll
            for (int i = 0; i < TM; i++) av[i] = sA[kk][trow * TM + i];
#pragma unroll
            for (int j = 0; j < TN; j++) bv[j] = sB[kk][tcol * TN + j];
#pragma unroll
            for (int i = 0; i < TM; i++)
#pragma unroll
                for (int j = 0; j < TN; j++)
                    acc[i][j] = fmaf(av[i], bv[j], acc[i][j]);
        }
        __syncthreads();
    }

#pragma unroll
    for (int i = 0; i < TM; i++) {
        int row = tm0 + trow * TM + i;
#pragma unroll
        for (int j = 0; j < TN; j++) {
            int col = tn0 + tcol * TN + j;
            float v = acc[i][j];
            long off = (long)row * ldc + col;
            if (EPI == 1) v += C[off];
            if (EPI == 3) v = fmaxf(v + bias[col], 0.f);
            if (EPI == 4) { if (col >= 1024) v += aux1[col - 1024]; }
            if (EPI == 5) {
                v += bias[col];
                if (col < 128)        v += aux1[(long)row * 128 + col]; // h_dst residual
                else if (col >= 192)  v += aux2[col - 192];             // cos(phase) residual
            }
            C[off] = v;
        }
    }
}

// ---------------- fused attention kernel: one block per dst node ----------------
__global__ void attn_kernel(const float* __restrict__ ef, const float* __restrict__ dt,
                            const int* __restrict__ nidx,
                            const float* __restrict__ freq, const float* __restrict__ ph)
{
    const int n = blockIdx.x;
    const int tid = threadIdx.x;
    __shared__ __align__(16) float s_qh[512];
    __shared__ __align__(16) float s_wf[1536];
    __shared__ __align__(16) float s_te[32][128];
    __shared__ __align__(16) float s_e[32][64];
    __shared__ float s_dt[32];
    __shared__ int   s_idx[32];
    __shared__ float s_fr[128], s_ph[128];
    __shared__ float s_at[8][32];

    for (int i = tid; i < 512;  i += 256) s_qh[i] = g_proj[(long)n * 1536 + 1024 + i];
    for (int i = tid; i < 1536; i += 256) s_wf[i] = g_wfold[(long)n * 1536 + i];
    for (int i = tid; i < 2048; i += 256) ((float*)s_e)[i] = ef[(long)n * 2048 + i];
    if (tid < 128) { s_fr[tid] = freq[tid]; s_ph[tid] = ph[tid]; }
    if (tid < 32)  { s_dt[tid] = dt[(long)n * 32 + tid]; s_idx[tid] = nidx[n * 16 + (tid >> 1)]; }
    __syncthreads();

    // temporal encoding
    for (int i = tid; i < 4096; i += 256) {
        int l = i >> 7, d = i & 127;
        s_te[l][d] = cosf(s_dt[l] * s_fr[d] + s_ph[d]);
    }
    __syncthreads();

    // scores + softmax: warp h handles head h, lane = l
    {
        const int h = tid >> 5, l = tid & 31;
        const float4* nk = (const float4*)(g_proj + (long)s_idx[l] * 1536 + h * 64);
        const float4* qv = (const float4*)(s_qh + h * 64);
        float sc = 0.f;
#pragma unroll
        for (int j = 0; j < 16; j++) {
            float4 a = qv[j], b = nk[j];
            sc += a.x * b.x + a.y * b.y + a.z * b.z + a.w * b.w;
        }
        const float4* ev = (const float4*)(s_e[l]);
        const float4* we = (const float4*)(s_wf + h * 192);
#pragma unroll
        for (int j = 0; j < 16; j++) {
            float4 a = ev[j], b = we[j];
            sc += a.x * b.x + a.y * b.y + a.z * b.z + a.w * b.w;
        }
        const float4* tv = (const float4*)(s_te[l]);
        const float4* wt = (const float4*)(s_wf + h * 192 + 64);
#pragma unroll
        for (int j = 0; j < 32; j++) {
            float4 a = tv[j], b = wt[j];
            sc += a.x * b.x + a.y * b.y + a.z * b.z + a.w * b.w;
        }
        sc *= 0.125f; // 1/sqrt(64)
        float mx = sc;
        for (int o = 16; o; o >>= 1) mx = fmaxf(mx, __shfl_xor_sync(0xffffffffu, mx, o));
        float ex = expf(sc - mx);
        float sm = ex;
        for (int o = 16; o; o >>= 1) sm += __shfl_xor_sync(0xffffffffu, sm, o);
        s_at[h][l] = ex / sm;
    }
    __syncthreads();

    // ctx node part: attn-weighted gather of node_v (coalesced over j)
    for (int j = tid; j < 512; j += 256) {
        int h = j >> 6;
        float a0 = 0.f;
#pragma unroll 4
        for (int l = 0; l < 32; l++)
            a0 += s_at[h][l] * g_proj[(long)s_idx[l] * 1536 + 512 + j];
        g_ctx[(long)n * 512 + j] = a0;
    }
    // ebar / tbar (pull attention through the linear V projection)
    for (int o = tid; o < 1536; o += 256) {
        int h = o / 192, c = o % 192;
        float a0 = 0.f;
        if (c < 64) {
#pragma unroll
            for (int l = 0; l < 32; l++) a0 += s_at[h][l] * s_e[l][c];
        } else {
            int d = c - 64;
#pragma unroll
            for (int l = 0; l < 32; l++) a0 += s_at[h][l] * s_te[l][d];
        }
        g_et[(long)n * 1536 + o] = a0;
    }
}

// ---------------- layernorm + concat ----------------
__global__ void ln_kernel(const float* __restrict__ lng, const float* __restrict__ lnb,
                          const float* __restrict__ nf)
{
    const int n = blockIdx.x, tid = threadIdx.x; // 128 threads
    float xv[3];
    int cnt = 0;
    float s = 0.f, sq = 0.f;
    for (int i = tid; i < 320; i += 128) {
        float v = g_x[(long)n * 320 + i];
        xv[cnt++] = v;
        s += v; sq += v * v;
    }
    __shared__ float rs[4], rq[4];
    for (int o = 16; o; o >>= 1) {
        s  += __shfl_xor_sync(0xffffffffu, s,  o);
        sq += __shfl_xor_sync(0xffffffffu, sq, o);
    }
    int wid = tid >> 5, lane = tid & 31;
    if (lane == 0) { rs[wid] = s; rq[wid] = sq; }
    __syncthreads();
    float ts = rs[0] + rs[1] + rs[2] + rs[3];
    float tq = rq[0] + rq[1] + rq[2] + rq[3];
    float mu = ts * (1.f / 320.f);
    float var = tq * (1.f / 320.f) - mu * mu;
    float inv = rsqrtf(var + 1e-5f);
    cnt = 0;
    for (int i = tid; i < 320; i += 128)
        g_hcat[(long)n * 448 + 128 + i] = lng[i] * (xv[cnt++] - mu) * inv + lnb[i];
    g_hcat[(long)n * 448 + tid] = nf[(long)n * 128 + tid];
}

// ---------------- launch ----------------
extern "C" void kernel_launch(void* const* d_in, const int* in_sizes, int n_in,
                              void* d_out, int out_size) {
    const float* nf   = (const float*)d_in[0];
    const float* ef   = (const float*)d_in[1];
    const float* dt   = (const float*)d_in[2];
    const int*   nidx = (const int*)  d_in[3];
    const float* freq = (const float*)d_in[4];
    const float* ph   = (const float*)d_in[5];
    const float* wqs  = (const float*)d_in[6];
    const float* wks  = (const float*)d_in[7];
    const float* wvs  = (const float*)d_in[8];
    const float* fcw  = (const float*)d_in[9];
    const float* fcb  = (const float*)d_in[10];
    const float* lng  = (const float*)d_in[11];
    const float* lnb  = (const float*)d_in[12];
    const float* nw   = (const float*)d_in[13];
    const float* nb   = (const float*)d_in[14];
    float* out = (float*)d_out;

    float *p_proj, *p_packW, *p_biasq, *p_cosph, *p_fcwT, *p_nodewT, *p_wvT,
          *p_wfold, *p_et, *p_ctx, *p_x, *p_hcat;
    cudaGetSymbolAddress((void**)&p_proj,   g_proj);
    cudaGetSymbolAddress((void**)&p_packW,  g_packW);
    cudaGetSymbolAddress((void**)&p_biasq,  g_biasq);
    cudaGetSymbolAddress((void**)&p_cosph,  g_cosph);
    cudaGetSymbolAddress((void**)&p_fcwT,   g_fcwT);
    cudaGetSymbolAddress((void**)&p_nodewT, g_nodewT);
    cudaGetSymbolAddress((void**)&p_wvT,    g_wvT);
    cudaGetSymbolAddress((void**)&p_wfold,  g_wfold);
    cudaGetSymbolAddress((void**)&p_et,     g_et);
    cudaGetSymbolAddress((void**)&p_ctx,    g_ctx);
    cudaGetSymbolAddress((void**)&p_x,      g_x);
    cudaGetSymbolAddress((void**)&p_hcat,   g_hcat);

    // 1) pack weights / bias
    prep_kernel<<<(516736 + 255) / 256, 256>>>(wks, wvs, wqs, fcw, nw, ph);

    // 2) node_k | node_v | qh projection: (16384 x 1536) = nf(16384x128) @ packW(128x1536)
    gemm_k<128,128,16,8,8,4><<<dim3(12,128,1), 256>>>(
        nf, p_packW, p_proj, N_SRC, 1536, 128, 128, 1536, 1536,
        0, 0, 0, nullptr, p_biasq, nullptr);

    // 3) fold q into K-weights, per head: (8192x192) = qh_h(8192x64) @ Wk_h(64x192)
    gemm_k<128,64,16,8,4,0><<<dim3(3,64,8), 256>>>(
        p_proj + 1024, wks + 128, p_wfold, N_DST, 192, 64, 1536, 320, 1536,
        64, (long)64 * 320, 192, nullptr, nullptr, nullptr);

    // 4) fused attention per dst: te, scores, softmax, ctx_node, ebar/tbar
    attn_kernel<<<N_DST, 256>>>(ef, dt, nidx, freq, ph);

    // 5) V projection (accumulate onto ctx_node): per head (8192x64) += et_h(8192x192) @ WvT_h(192x64)
    gemm_k<128,64,16,8,4,1><<<dim3(1,64,8), 256>>>(
        p_et, p_wvT, p_ctx, N_DST, 64, 192, 1536, 64, 512,
        192, (long)192 * 64, 64, nullptr, nullptr, nullptr);

    // 6) fc: x = ctx @ fc_w^T + fc_b + q  (residual fused in epilogue)
    gemm_k<128,64,16,8,4,5><<<dim3(5,64,1), 256>>>(
        p_ctx, p_fcwT, p_x, N_DST, 320, 512, 512, 320, 320,
        0, 0, 0, fcb, nf, p_cosph);

    // 7) layernorm + concat [h_dst | h_neigh]
    ln_kernel<<<N_DST, 128>>>(lng, lnb, nf);

    // 8) final: relu(hcat @ node_w^T + node_b)
    gemm_k<128,64,16,8,4,3><<<dim3(2,64,1), 256>>>(
        p_hcat, p_nodewT, out, N_DST, 128, 448, 448, 128, 128,
        0, 0, 0, nb, nullptr, nullptr);
}

// round 2
// speedup vs baseline: 1.5994x; 1.5994x over previous
#include <cuda_runtime.h>
#include <math.h>

#define N_SRC   16384
#define N_DST   8192
#define NODE_IN 128
#define EDGE_IN 64
#define TIME_D  128
#define D_MODEL 320
#define NH      8
#define DK      64
#define HID     128

// ---------------- scratch (device globals; no allocations) ----------------
__device__ float g_proj[(long)N_SRC * 1536];   // [0:512) node_k | [512:1024) node_v | [1024:1536) qh
__device__ float g_packW[128 * 1536];
__device__ float g_biasq[512];
__device__ float g_cosph[128];
__device__ float g_fcwT[512 * 320];
__device__ float g_nodewT[448 * 128];
__device__ float g_wvT[8 * 192 * 64];
__device__ float g_wfold[(long)N_DST * 1536];
__device__ float g_et[(long)N_DST * 1536];
__device__ float g_ctx[(long)N_DST * 512];
__device__ float g_x[(long)N_DST * 320];
__device__ float g_hcat[(long)N_DST * 448];

// ---------------- f32x2 packed-FMA helpers ----------------
__device__ __forceinline__ unsigned long long pack2(float x, float y) {
    unsigned long long r;
    asm("mov.b64 %0, {%1, %2};" : "=l"(r) : "f"(x), "f"(y));
    return r;
}
__device__ __forceinline__ void unpack2(unsigned long long v, float& x, float& y) {
    asm("mov.b64 {%0, %1}, %2;" : "=f"(x), "=f"(y) : "l"(v));
}
__device__ __forceinline__ void ffma2(unsigned long long& d, unsigned long long a, unsigned long long b) {
    asm("fma.rn.f32x2 %0, %1, %2, %0;" : "+l"(d) : "l"(a), "l"(b));
}

// ---------------- prep / pack kernel ----------------
__global__ void prep_kernel(const float* __restrict__ wks, const float* __restrict__ wvs,
                            const float* __restrict__ wqs, const float* __restrict__ fcw,
                            const float* __restrict__ nw,  const float* __restrict__ ph)
{
    const int P0 = 196608;
    const int P1 = P0 + 163840;
    const int P2 = P1 + 57344;
    const int P3 = P2 + 98304;
    const int P4 = P3 + 512;
    const int P5 = P4 + 128;
    int t = blockIdx.x * blockDim.x + threadIdx.x;
    if (t < P0) {
        int d = t / 1536, r = t % 1536;
        float v;
        if (r < 512)       v = wks[r * 320 + d];
        else if (r < 1024) v = wvs[(r - 512) * 320 + d];
        else               v = wqs[(r - 1024) * 320 + d];
        g_packW[t] = v;
    } else if (t < P1) {
        int i = t - P0; int j = i / 320, c = i % 320;
        g_fcwT[i] = fcw[c * 512 + j];
    } else if (t < P2) {
        int i = t - P1; int c = i / 128, o = i % 128;
        g_nodewT[i] = nw[o * 448 + c];
    } else if (t < P3) {
        int i = t - P2; int h = i / 12288; int rem = i % 12288;
        int c = rem / 64, d = rem % 64;
        g_wvT[i] = wvs[(h * 64 + d) * 320 + 128 + c];
    } else if (t < P4) {
        int j = t - P3;
        float acc = 0.f;
        for (int d = 0; d < 128; d++) acc += cosf(ph[d]) * wqs[j * 320 + 192 + d];
        g_biasq[j] = acc;
    } else if (t < P5) {
        int d = t - P4;
        g_cosph[d] = cosf(ph[d]);
    }
}

// ---------------- register-tiled SGEMM with packed f32x2 FMA ----------------
// TM must be 8, TN in {4,8}. All dims tile multiples (true for all calls).
// EPI: 0 store, 1 accumulate, 3 relu(v+bias), 4 qh-bias (col>=1024), 5 fc epilogue
template<int BM, int BN, int BK, int TM, int TN, int EPI>
__global__ void gemm_k(const float* __restrict__ A, const float* __restrict__ B,
                       float* __restrict__ C,
                       int M, int N, int Kd, int lda, int ldb, int ldc,
                       long bsA, long bsB, long bsC,
                       const float* __restrict__ bias,
                       const float* __restrict__ aux1,
                       const float* __restrict__ aux2)
{
    constexpr int THREADS = (BM / TM) * (BN / TN);
    __shared__ __align__(16) float sA[BK][BM + 4];
    __shared__ __align__(16) float sB[BK][BN + 4];
    const int bz = blockIdx.z;
    A += (long)bz * bsA; B += (long)bz * bsB; C += (long)bz * bsC;
    const int tm0 = blockIdx.y * BM;
    const int tn0 = blockIdx.x * BN;
    const int tid = threadIdx.x;
    const int tcol = tid % (BN / TN);
    const int trow = tid / (BN / TN);

    unsigned long long acc2[TM][TN / 2];
#pragma unroll
    for (int i = 0; i < TM; i++)
#pragma unroll
        for (int j = 0; j < TN / 2; j++) acc2[i][j] = 0ull;

    for (int k0 = 0; k0 < Kd; k0 += BK) {
        // stage A (transposed) with float4 global loads
        constexpr int AITER = (BM * BK / 4 + THREADS - 1) / THREADS;
#pragma unroll
        for (int it = 0; it < AITER; it++) {
            int idx = tid + it * THREADS;
            if (idx < BM * BK / 4) {
                int m = idx >> 2, q = idx & 3;
                float4 v = *(const float4*)&A[(long)(tm0 + m) * lda + k0 + q * 4];
                sA[q * 4 + 0][m] = v.x;
                sA[q * 4 + 1][m] = v.y;
                sA[q * 4 + 2][m] = v.z;
                sA[q * 4 + 3][m] = v.w;
            }
        }
        // stage B with float4
        constexpr int BITER = (BK * BN / 4 + THREADS - 1) / THREADS;
#pragma unroll
        for (int it = 0; it < BITER; it++) {
            int idx = tid + it * THREADS;
            if (idx < BK * BN / 4) {
                int kk = idx / (BN / 4), n4 = idx % (BN / 4);
                float4 v = *(const float4*)&B[(long)(k0 + kk) * ldb + tn0 + n4 * 4];
                *(float4*)&sB[kk][n4 * 4] = v;
            }
        }
        __syncthreads();
#pragma unroll
        for (int kk = 0; kk < BK; kk++) {
            float4 a0 = *(const float4*)&sA[kk][trow * TM];
            float4 a1 = *(const float4*)&sA[kk][trow * TM + 4];
            float av[8] = {a0.x, a0.y, a0.z, a0.w, a1.x, a1.y, a1.z, a1.w};
            unsigned long long b2[TN / 2];
            {
                float4 bx = *(const float4*)&sB[kk][tcol * TN];
                b2[0] = pack2(bx.x, bx.y);
                b2[1] = pack2(bx.z, bx.w);
                if (TN == 8) {
                    float4 by = *(const float4*)&sB[kk][tcol * TN + 4];
                    b2[2] = pack2(by.x, by.y);
                    b2[3] = pack2(by.z, by.w);
                }
            }
#pragma unroll
            for (int i = 0; i < TM; i++) {
                unsigned long long a2 = pack2(av[i], av[i]);
#pragma unroll
                for (int j = 0; j < TN / 2; j++) ffma2(acc2[i][j], a2, b2[j]);
            }
        }
        __syncthreads();
    }

#pragma unroll
    for (int i = 0; i < TM; i++) {
        int row = tm0 + trow * TM + i;
#pragma unroll
        for (int j2 = 0; j2 < TN / 2; j2++) {
            float v0, v1;
            unpack2(acc2[i][j2], v0, v1);
#pragma unroll
            for (int s = 0; s < 2; s++) {
                float v = s ? v1 : v0;
                int col = tn0 + tcol * TN + j2 * 2 + s;
                long off = (long)row * ldc + col;
                if (EPI == 1) v += C[off];
                if (EPI == 3) v = fmaxf(v + bias[col], 0.f);
                if (EPI == 4) { if (col >= 1024) v += aux1[col - 1024]; }
                if (EPI == 5) {
                    v += bias[col];
                    if (col < 128)        v += aux1[(long)row * 128 + col];
                    else if (col >= 192)  v += aux2[col - 192];
                }
                C[off] = v;
            }
        }
    }
}

// ---------------- fused attention kernel: one block per dst node ----------------
// Shared rows padded to stride%32==4 for conflict-free LDS.128 across lanes.
__global__ void attn_kernel(const float* __restrict__ ef, const float* __restrict__ dt,
                            const int* __restrict__ nidx,
                            const float* __restrict__ freq, const float* __restrict__ ph)
{
    const int n = blockIdx.x;
    const int tid = threadIdx.x;
    __shared__ __align__(16) float s_qh[512];
    __shared__ __align__(16) float s_wf[1536];
    __shared__ __align__(16) float s_te[32][132];   // stride 132: conflict-free float4
    __shared__ __align__(16) float s_e[32][68];     // stride 68:  conflict-free float4
    __shared__ float s_dt[32];
    __shared__ int   s_idx[32];
    __shared__ float s_fr[128], s_ph[128];
    __shared__ float s_at[8][33];

    for (int i = tid; i < 512;  i += 256) s_qh[i] = g_proj[(long)n * 1536 + 1024 + i];
    for (int i = tid; i < 1536; i += 256) s_wf[i] = g_wfold[(long)n * 1536 + i];
    // edge features: 2048 floats = 512 float4
    {
        const float4* ef4 = (const float4*)(ef + (long)n * 2048);
        for (int i = tid; i < 512; i += 256) {
            int l = i >> 4, c4 = i & 15;
            *(float4*)&s_e[l][c4 * 4] = ef4[i];
        }
    }
    if (tid < 128) { s_fr[tid] = freq[tid]; s_ph[tid] = ph[tid]; }
    if (tid < 32)  { s_dt[tid] = dt[(long)n * 32 + tid]; s_idx[tid] = nidx[n * 16 + (tid >> 1)]; }
    __syncthreads();

    // temporal encoding (exact cosf, FMA-pipe polynomial)
    for (int i = tid; i < 4096; i += 256) {
        int l = i >> 7, d = i & 127;
        s_te[l][d] = cosf(s_dt[l] * s_fr[d] + s_ph[d]);
    }
    __syncthreads();

    // scores + softmax: warp h handles head h, lane = l
    {
        const int h = tid >> 5, l = tid & 31;
        const float4* nk = (const float4*)(g_proj + (long)s_idx[l] * 1536 + h * 64);
        const float4* qv = (const float4*)(s_qh + h * 64);
        float sc = 0.f;
#pragma unroll
        for (int j = 0; j < 16; j++) {
            float4 a = qv[j], b = nk[j];
            sc += a.x * b.x + a.y * b.y + a.z * b.z + a.w * b.w;
        }
        const float4* ev = (const float4*)(&s_e[l][0]);
        const float4* we = (const float4*)(s_wf + h * 192);
#pragma unroll
        for (int j = 0; j < 16; j++) {
            float4 a = ev[j], b = we[j];
            sc += a.x * b.x + a.y * b.y + a.z * b.z + a.w * b.w;
        }
        const float4* tv = (const float4*)(&s_te[l][0]);
        const float4* wt = (const float4*)(s_wf + h * 192 + 64);
#pragma unroll
        for (int j = 0; j < 32; j++) {
            float4 a = tv[j], b = wt[j];
            sc += a.x * b.x + a.y * b.y + a.z * b.z + a.w * b.w;
        }
        sc *= 0.125f; // 1/sqrt(64)
        float mx = sc;
        for (int o = 16; o; o >>= 1) mx = fmaxf(mx, __shfl_xor_sync(0xffffffffu, mx, o));
        float ex = expf(sc - mx);
        float sm = ex;
        for (int o = 16; o; o >>= 1) sm += __shfl_xor_sync(0xffffffffu, sm, o);
        s_at[h][l] = ex / sm;
    }
    __syncthreads();

    // ctx node part: attn-weighted gather of node_v (coalesced over j)
    for (int j = tid; j < 512; j += 256) {
        int h = j >> 6;
        float a0 = 0.f;
#pragma unroll 4
        for (int l = 0; l < 32; l++)
            a0 += s_at[h][l] * g_proj[(long)s_idx[l] * 1536 + 512 + j];
        g_ctx[(long)n * 512 + j] = a0;
    }
    // ebar / tbar
    for (int o = tid; o < 1536; o += 256) {
        int h = o / 192, c = o % 192;
        float a0 = 0.f;
        if (c < 64) {
#pragma unroll
            for (int l = 0; l < 32; l++) a0 += s_at[h][l] * s_e[l][c];
        } else {
            int d = c - 64;
#pragma unroll
            for (int l = 0; l < 32; l++) a0 += s_at[h][l] * s_te[l][d];
        }
        g_et[(long)n * 1536 + o] = a0;
    }
}

// ---------------- layernorm + concat ----------------
__global__ void ln_kernel(const float* __restrict__ lng, const float* __restrict__ lnb,
                          const float* __restrict__ nf)
{
    const int n = blockIdx.x, tid = threadIdx.x; // 128 threads
    float xv[3];
    int cnt = 0;
    float s = 0.f, sq = 0.f;
    for (int i = tid; i < 320; i += 128) {
        float v = g_x[(long)n * 320 + i];
        xv[cnt++] = v;
        s += v; sq += v * v;
    }
    __shared__ float rs[4], rq[4];
    for (int o = 16; o; o >>= 1) {
        s  += __shfl_xor_sync(0xffffffffu, s,  o);
        sq += __shfl_xor_sync(0xffffffffu, sq, o);
    }
    int wid = tid >> 5, lane = tid & 31;
    if (lane == 0) { rs[wid] = s; rq[wid] = sq; }
    __syncthreads();
    float ts = rs[0] + rs[1] + rs[2] + rs[3];
    float tq = rq[0] + rq[1] + rq[2] + rq[3];
    float mu = ts * (1.f / 320.f);
    float var = tq * (1.f / 320.f) - mu * mu;
    float inv = rsqrtf(var + 1e-5f);
    cnt = 0;
    for (int i = tid; i < 320; i += 128)
        g_hcat[(long)n * 448 + 128 + i] = lng[i] * (xv[cnt++] - mu) * inv + lnb[i];
    g_hcat[(long)n * 448 + tid] = nf[(long)n * 128 + tid];
}

// ---------------- launch ----------------
extern "C" void kernel_launch(void* const* d_in, const int* in_sizes, int n_in,
                              void* d_out, int out_size) {
    const float* nf   = (const float*)d_in[0];
    const float* ef   = (const float*)d_in[1];
    const float* dt   = (const float*)d_in[2];
    const int*   nidx = (const int*)  d_in[3];
    const float* freq = (const float*)d_in[4];
    const float* ph   = (const float*)d_in[5];
    const float* wqs  = (const float*)d_in[6];
    const float* wks  = (const float*)d_in[7];
    const float* wvs  = (const float*)d_in[8];
    const float* fcw  = (const float*)d_in[9];
    const float* fcb  = (const float*)d_in[10];
    const float* lng  = (const float*)d_in[11];
    const float* lnb  = (const float*)d_in[12];
    const float* nw   = (const float*)d_in[13];
    const float* nb   = (const float*)d_in[14];
    float* out = (float*)d_out;

    float *p_proj, *p_packW, *p_biasq, *p_cosph, *p_fcwT, *p_nodewT, *p_wvT,
          *p_wfold, *p_et, *p_ctx, *p_x, *p_hcat;
    cudaGetSymbolAddress((void**)&p_proj,   g_proj);
    cudaGetSymbolAddress((void**)&p_packW,  g_packW);
    cudaGetSymbolAddress((void**)&p_biasq,  g_biasq);
    cudaGetSymbolAddress((void**)&p_cosph,  g_cosph);
    cudaGetSymbolAddress((void**)&p_fcwT,   g_fcwT);
    cudaGetSymbolAddress((void**)&p_nodewT, g_nodewT);
    cudaGetSymbolAddress((void**)&p_wvT,    g_wvT);
    cudaGetSymbolAddress((void**)&p_wfold,  g_wfold);
    cudaGetSymbolAddress((void**)&p_et,     g_et);
    cudaGetSymbolAddress((void**)&p_ctx,    g_ctx);
    cudaGetSymbolAddress((void**)&p_x,      g_x);
    cudaGetSymbolAddress((void**)&p_hcat,   g_hcat);

    // 1) pack weights / bias
    prep_kernel<<<(516736 + 255) / 256, 256>>>(wks, wvs, wqs, fcw, nw, ph);

    // 2) node_k | node_v | qh projection: (16384 x 1536) = nf(16384x128) @ packW(128x1536)
    gemm_k<128,128,16,8,8,4><<<dim3(12,128,1), 256>>>(
        nf, p_packW, p_proj, N_SRC, 1536, 128, 128, 1536, 1536,
        0, 0, 0, nullptr, p_biasq, nullptr);

    // 3) fold q into K-weights, per head: (8192x192) = qh_h(8192x64) @ Wk_h(64x192)
    gemm_k<128,64,16,8,4,0><<<dim3(3,64,8), 256>>>(
        p_proj + 1024, wks + 128, p_wfold, N_DST, 192, 64, 1536, 320, 1536,
        64, (long)64 * 320, 192, nullptr, nullptr, nullptr);

    // 4) fused attention per dst
    attn_kernel<<<N_DST, 256>>>(ef, dt, nidx, freq, ph);

    // 5) V projection (accumulate): per head (8192x64) += et_h(8192x192) @ WvT_h(192x64)
    gemm_k<128,64,16,8,4,1><<<dim3(1,64,8), 256>>>(
        p_et, p_wvT, p_ctx, N_DST, 64, 192, 1536, 64, 512,
        192, (long)192 * 64, 64, nullptr, nullptr, nullptr);

    // 6) fc: x = ctx @ fc_w^T + fc_b + q  (residual fused)
    gemm_k<128,64,16,8,4,5><<<dim3(5,64,1), 256>>>(
        p_ctx, p_fcwT, p_x, N_DST, 320, 512, 512, 320, 320,
        0, 0, 0, fcb, nf, p_cosph);

    // 7) layernorm + concat
    ln_kernel<<<N_DST, 128>>>(lng, lnb, nf);

    // 8) final: relu(hcat @ node_w^T + node_b)
    gemm_k<128,64,16,8,4,3><<<dim3(2,64,1), 256>>>(
        p_hcat, p_nodewT, out, N_DST, 128, 448, 448, 128, 128,
        0, 0, 0, nb, nullptr, nullptr);
}